// round 2
// baseline (speedup 1.0000x reference)
#include <cuda_runtime.h>
#include <cstdint>
#include <math.h>

#define D_  512
#define NB_ 2048
#define TT_ 64
#define MT_ (NB_*TT_)

// ---------------- scratch (device globals) ----------------
__device__ __align__(16) float g_xproj[(size_t)MT_ * 1536];
__device__ __align__(16) uint2 g_W1_hl[1536 * D_];   // concat(Wzx,Wrx,Whx) as (hi,lo) tf32
__device__ __align__(16) uint2 g_Wg_hl[1024 * D_];   // concat(Wzh,Wrh)
__device__ __align__(16) uint2 g_Wh_hl[D_ * D_];     // Whh
__device__ __align__(16) float g_bias[1536];
__device__ __align__(16) float g_h[NB_ * D_];
__device__ __align__(16) float g_z[NB_ * D_];
__device__ __align__(16) float g_u[NB_ * D_];

// ---------------- helpers ----------------
__device__ __forceinline__ unsigned f2t(float x) {
    unsigned r;
    asm("cvt.rna.tf32.f32 %0, %1;" : "=r"(r) : "f"(x));
    return r;
}
__device__ __forceinline__ uint2 f2hl(float x) {
    unsigned hi = f2t(x);
    unsigned lo = f2t(x - __uint_as_float(hi));
    return make_uint2(hi, lo);
}
__device__ __forceinline__ void mma8(float* d, const unsigned* a, const unsigned* b) {
    asm volatile(
        "mma.sync.aligned.m16n8k8.row.col.f32.tf32.tf32.f32 "
        "{%0,%1,%2,%3},{%4,%5,%6,%7},{%8,%9},{%0,%1,%2,%3};"
        : "+f"(d[0]), "+f"(d[1]), "+f"(d[2]), "+f"(d[3])
        : "r"(a[0]), "r"(a[1]), "r"(a[2]), "r"(a[3]), "r"(b[0]), "r"(b[1]));
}
__device__ __forceinline__ float sigmoidf_(float x) { return 1.0f / (1.0f + expf(-x)); }

// ---------------- prep ----------------
__global__ void prep_kernel(const float* __restrict__ Wzx, const float* __restrict__ Wzh,
                            const float* __restrict__ Wrx, const float* __restrict__ Wrh,
                            const float* __restrict__ Whx, const float* __restrict__ Whh,
                            const float* __restrict__ bz, const float* __restrict__ br,
                            const float* __restrict__ bh) {
    int i = blockIdx.x * blockDim.x + threadIdx.x;
    const int WN = D_ * D_;
    if (i < WN) {
        g_W1_hl[i]          = f2hl(Wzx[i]);
        g_W1_hl[WN + i]     = f2hl(Wrx[i]);
        g_W1_hl[2 * WN + i] = f2hl(Whx[i]);
        g_Wg_hl[i]          = f2hl(Wzh[i]);
        g_Wg_hl[WN + i]     = f2hl(Wrh[i]);
        g_Wh_hl[i]          = f2hl(Whh[i]);
    }
    if (i < 1536) g_bias[i] = (i < 512) ? bz[i] : (i < 1024 ? br[i - 512] : bh[i - 1024]);
    if (i < NB_ * D_) g_h[i] = 0.0f;
}

// ---------------- fused tf32x3 GEMM ----------------
// C[M,N] = A[M,512] * B[N,512]^T.  CTA tile: BM x 128, 256 threads, warps 2x4.
// MODE 0: A=X,   B=W1,  -> g_xproj (+bias)
// MODE 1: A=g_h, B=Wg,  -> z=sigm(.+xz)->g_z ; u=sigm(.+xr)*h->g_u
// MODE 2: A=g_u, B=Whh, -> ht=tanh(.+xh); h=z*h+(1-z)*ht -> g_h, out
template <int MODE, int BM>
__global__ __launch_bounds__(256, 1) void gemm_k(const float* __restrict__ A_arg,
                                                 float* __restrict__ out, int t) {
    extern __shared__ uint2 sm2[];
    const int ASTRIDE = BM * 36;
    const int BSTRIDE = 128 * 36;
    const int MI = BM / 32;                 // i-tiles per warp (warptile BM/2 x 32)
    uint2* As = sm2;                        // [2][BM*36]  (hi,lo) interleaved
    uint2* Bs = sm2 + 2 * ASTRIDE;          // [2][128*36]

    const float* __restrict__ A = (MODE == 0) ? A_arg : (MODE == 1 ? g_h : g_u);
    const uint2* __restrict__ Bhl = (MODE == 0) ? g_W1_hl : (MODE == 1 ? g_Wg_hl : g_Wh_hl);

    const int tid  = threadIdx.x;
    const int lane = tid & 31, warp = tid >> 5;
    const int wm = warp >> 2, wn = warp & 3;
    const int g  = lane >> 2, tg = lane & 3;
    const int bm = blockIdx.y * BM, bn = blockIdx.x * 128;

    const int lrow = tid >> 3;            // 0..31
    const int lcol = (tid & 7) << 2;      // 0,4,...,28

    const float* Ag = A + (size_t)(bm + lrow) * D_ + lcol;
    const uint2* Bg = Bhl + (size_t)(bn + lrow) * D_ + lcol;

    float acc[BM / 32][4][4];
#pragma unroll
    for (int i = 0; i < MI; i++)
#pragma unroll
        for (int j = 0; j < 4; j++)
#pragma unroll
            for (int e = 0; e < 4; e++) acc[i][j][e] = 0.0f;

    float4 ra[BM / 32];
    uint4  rb0[4], rb1[4];

#pragma unroll
    for (int i = 0; i < MI; i++) ra[i] = *(const float4*)(Ag + (size_t)i * 32 * D_);
#pragma unroll
    for (int i = 0; i < 4; i++) {
        rb0[i] = *(const uint4*)(Bg + (size_t)i * 32 * D_);
        rb1[i] = *(const uint4*)(Bg + (size_t)i * 32 * D_ + 2);
    }
#pragma unroll
    for (int i = 0; i < MI; i++) {
        uint2 h0 = f2hl(ra[i].x), h1 = f2hl(ra[i].y), h2 = f2hl(ra[i].z), h3 = f2hl(ra[i].w);
        uint2* dst = &As[(lrow + i * 32) * 36 + lcol];
        *(uint4*)(dst)     = make_uint4(h0.x, h0.y, h1.x, h1.y);
        *(uint4*)(dst + 2) = make_uint4(h2.x, h2.y, h3.x, h3.y);
    }
#pragma unroll
    for (int i = 0; i < 4; i++) {
        uint2* dst = &Bs[(lrow + i * 32) * 36 + lcol];
        *(uint4*)(dst)     = rb0[i];
        *(uint4*)(dst + 2) = rb1[i];
    }
    __syncthreads();

    int buf = 0;
#pragma unroll 1
    for (int kt = 0; kt < 16; kt++) {
        if (kt < 15) {
            const float* Ag2 = Ag + (kt + 1) * 32;
            const uint2* Bg2 = Bg + (kt + 1) * 32;
#pragma unroll
            for (int i = 0; i < MI; i++) ra[i] = *(const float4*)(Ag2 + (size_t)i * 32 * D_);
#pragma unroll
            for (int i = 0; i < 4; i++) {
                rb0[i] = *(const uint4*)(Bg2 + (size_t)i * 32 * D_);
                rb1[i] = *(const uint4*)(Bg2 + (size_t)i * 32 * D_ + 2);
            }
        }
        const uint2* Ab = As + buf * ASTRIDE;
        const uint2* Bb = Bs + buf * BSTRIDE;
#pragma unroll
        for (int kk = 0; kk < 4; kk++) {
            const int k0 = kk * 8;
            uint2 aa[BM / 32][4], bb[4][2];
#pragma unroll
            for (int i = 0; i < MI; i++) {
                const int r0 = wm * (BM / 2) + i * 16 + g;
                aa[i][0] = Ab[r0 * 36 + k0 + tg];
                aa[i][1] = Ab[(r0 + 8) * 36 + k0 + tg];
                aa[i][2] = Ab[r0 * 36 + k0 + tg + 4];
                aa[i][3] = Ab[(r0 + 8) * 36 + k0 + tg + 4];
            }
#pragma unroll
            for (int j = 0; j < 4; j++) {
                const int n0 = wn * 32 + j * 8 + g;
                bb[j][0] = Bb[n0 * 36 + k0 + tg];
                bb[j][1] = Bb[n0 * 36 + k0 + tg + 4];
            }
            // tf32x3: hi*hi, lo*hi, hi*lo
#pragma unroll
            for (int i = 0; i < MI; i++) {
                unsigned ahi[4] = {aa[i][0].x, aa[i][1].x, aa[i][2].x, aa[i][3].x};
#pragma unroll
                for (int j = 0; j < 4; j++) {
                    unsigned bhi[2] = {bb[j][0].x, bb[j][1].x};
                    mma8(acc[i][j], ahi, bhi);
                }
            }
#pragma unroll
            for (int i = 0; i < MI; i++) {
                unsigned alo[4] = {aa[i][0].y, aa[i][1].y, aa[i][2].y, aa[i][3].y};
#pragma unroll
                for (int j = 0; j < 4; j++) {
                    unsigned bhi[2] = {bb[j][0].x, bb[j][1].x};
                    mma8(acc[i][j], alo, bhi);
                }
            }
#pragma unroll
            for (int i = 0; i < MI; i++) {
                unsigned ahi[4] = {aa[i][0].x, aa[i][1].x, aa[i][2].x, aa[i][3].x};
#pragma unroll
                for (int j = 0; j < 4; j++) {
                    unsigned blo[2] = {bb[j][0].y, bb[j][1].y};
                    mma8(acc[i][j], ahi, blo);
                }
            }
        }
        if (kt < 15) {
            __syncthreads();
            uint2* An = As + (buf ^ 1) * ASTRIDE;
            uint2* Bn = Bs + (buf ^ 1) * BSTRIDE;
#pragma unroll
            for (int i = 0; i < MI; i++) {
                uint2 h0 = f2hl(ra[i].x), h1 = f2hl(ra[i].y), h2 = f2hl(ra[i].z), h3 = f2hl(ra[i].w);
                uint2* dst = &An[(lrow + i * 32) * 36 + lcol];
                *(uint4*)(dst)     = make_uint4(h0.x, h0.y, h1.x, h1.y);
                *(uint4*)(dst + 2) = make_uint4(h2.x, h2.y, h3.x, h3.y);
            }
#pragma unroll
            for (int i = 0; i < 4; i++) {
                uint2* dst = &Bn[(lrow + i * 32) * 36 + lcol];
                *(uint4*)(dst)     = rb0[i];
                *(uint4*)(dst + 2) = rb1[i];
            }
            __syncthreads();
        }
        buf ^= 1;
    }

    // ---------------- epilogue ----------------
#pragma unroll
    for (int i = 0; i < MI; i++) {
#pragma unroll
        for (int j = 0; j < 4; j++) {
#pragma unroll
            for (int e = 0; e < 4; e++) {
                const int row = bm + wm * (BM / 2) + i * 16 + g + ((e >> 1) << 3);
                const int col = bn + wn * 32 + j * 8 + (tg << 1) + (e & 1);
                float v = acc[i][j][e];
                if (MODE == 0) {
                    v += g_bias[col];
                    g_xproj[(size_t)row * 1536 + col] = v;
                } else if (MODE == 1) {
                    const size_t xb = ((size_t)row * TT_ + t) * 1536;
                    if (col < 512) {
                        g_z[row * D_ + col] = sigmoidf_(v + g_xproj[xb + col]);
                    } else {
                        const int c = col - 512;
                        float rr = sigmoidf_(v + g_xproj[xb + 512 + c]);
                        g_u[row * D_ + c] = rr * g_h[row * D_ + c];
                    }
                } else {
                    const size_t xb = ((size_t)row * TT_ + t) * 1536;
                    float ht = tanhf(v + g_xproj[xb + 1024 + col]);
                    float zz = g_z[row * D_ + col];
                    float ho = g_h[row * D_ + col];
                    float hn = zz * ho + (1.0f - zz) * ht;
                    g_h[row * D_ + col] = hn;
                    out[((size_t)row * TT_ + t) * D_ + col] = hn;
                }
            }
        }
    }
}

// ---------------- launch ----------------
extern "C" void kernel_launch(void* const* d_in, const int* in_sizes, int n_in,
                              void* d_out, int out_size) {
    const float* X   = (const float*)d_in[0];
    const float* Wzx = (const float*)d_in[1];
    const float* Wzh = (const float*)d_in[2];
    const float* Wrx = (const float*)d_in[3];
    const float* Wrh = (const float*)d_in[4];
    const float* Whx = (const float*)d_in[5];
    const float* Whh = (const float*)d_in[6];
    const float* bz  = (const float*)d_in[7];
    const float* br  = (const float*)d_in[8];
    const float* bh  = (const float*)d_in[9];
    float* out = (float*)d_out;

    const int SMEM128 = (2 * 128 * 36 + 2 * 128 * 36) * (int)sizeof(uint2); // 147456
    const int SMEM64  = (2 * 64 * 36 + 2 * 128 * 36) * (int)sizeof(uint2);  // 110592
    cudaFuncSetAttribute((const void*)gemm_k<0, 128>, cudaFuncAttributeMaxDynamicSharedMemorySize, SMEM128);
    cudaFuncSetAttribute((const void*)gemm_k<1, 128>, cudaFuncAttributeMaxDynamicSharedMemorySize, SMEM128);
    cudaFuncSetAttribute((const void*)gemm_k<2, 64>,  cudaFuncAttributeMaxDynamicSharedMemorySize, SMEM64);

    prep_kernel<<<(NB_ * D_ + 255) / 256, 256>>>(Wzx, Wzh, Wrx, Wrh, Whx, Whh, bz, br, bh);

    // Phase 1: time-parallel input projections [131072 x 1536]
    gemm_k<0, 128><<<dim3(1536 / 128, MT_ / 128), 256, SMEM128>>>(X, out, 0);

    // Phase 2: sequential recurrence (full-chip grids: 128 CTAs each)
    for (int t = 0; t < TT_; t++) {
        gemm_k<1, 128><<<dim3(1024 / 128, NB_ / 128), 256, SMEM128>>>(X, out, t);
        gemm_k<2, 64><<<dim3(512 / 128, NB_ / 64), 256, SMEM64>>>(X, out, t);
    }
}

// round 3
// speedup vs baseline: 1.7799x; 1.7799x over previous
#include <cuda_runtime.h>
#include <cuda_fp16.h>
#include <cstdint>
#include <math.h>

#define D_  512
#define NB_ 2048
#define TT_ 64
#define MT_ (NB_*TT_)
#define KP_ (D_/2)          // 256 k-pairs per row
#define WN2 (D_*D_/2)       // uint2 elements per weight matrix

// ---------------- scratch (device globals) ----------------
__device__ __align__(16) float g_xproj[(size_t)MT_ * 1536];
__device__ __align__(16) uint2 g_W1h[1536 * KP_];   // concat(Wzx,Wrx,Whx): (hi half2, lo half2) per k-pair
__device__ __align__(16) uint2 g_Wgh[1024 * KP_];   // concat(Wzh,Wrh)
__device__ __align__(16) uint2 g_Whh[512 * KP_];    // Whh
__device__ __align__(16) float g_bias[1536];
__device__ __align__(16) float g_h[NB_ * D_];
__device__ __align__(16) float g_z[NB_ * D_];
__device__ __align__(16) float g_u[NB_ * D_];

// ---------------- helpers ----------------
__device__ __forceinline__ uint2 f2hl2(float x0, float x1) {
    half h0 = __float2half_rn(x0);
    half h1 = __float2half_rn(x1);
    half l0 = __float2half_rn(x0 - __half2float(h0));
    half l1 = __float2half_rn(x1 - __half2float(h1));
    __half2 hh = __halves2half2(h0, h1);
    __half2 ll = __halves2half2(l0, l1);
    uint2 r;
    r.x = *reinterpret_cast<unsigned*>(&hh);
    r.y = *reinterpret_cast<unsigned*>(&ll);
    return r;
}

__device__ __forceinline__ void mma16(float* d, const unsigned* a, const unsigned* b) {
    asm volatile(
        "mma.sync.aligned.m16n8k16.row.col.f32.f16.f16.f32 "
        "{%0,%1,%2,%3},{%4,%5,%6,%7},{%8,%9},{%0,%1,%2,%3};"
        : "+f"(d[0]), "+f"(d[1]), "+f"(d[2]), "+f"(d[3])
        : "r"(a[0]), "r"(a[1]), "r"(a[2]), "r"(a[3]), "r"(b[0]), "r"(b[1]));
}
__device__ __forceinline__ float sigmoidf_(float x) { return 1.0f / (1.0f + expf(-x)); }

// ---------------- prep: convert weights to fp16 hi/lo pairs ----------------
__global__ void prep_kernel(const float* __restrict__ Wzx, const float* __restrict__ Wzh,
                            const float* __restrict__ Wrx, const float* __restrict__ Wrh,
                            const float* __restrict__ Whx, const float* __restrict__ Whh,
                            const float* __restrict__ bz, const float* __restrict__ br,
                            const float* __restrict__ bh) {
    int i = blockIdx.x * blockDim.x + threadIdx.x;
    if (i < WN2) {
        int n = i >> 8, kp = i & (KP_ - 1);
        int s = n * D_ + 2 * kp;
        g_W1h[i]           = f2hl2(Wzx[s], Wzx[s + 1]);
        g_W1h[WN2 + i]     = f2hl2(Wrx[s], Wrx[s + 1]);
        g_W1h[2 * WN2 + i] = f2hl2(Whx[s], Whx[s + 1]);
        g_Wgh[i]           = f2hl2(Wzh[s], Wzh[s + 1]);
        g_Wgh[WN2 + i]     = f2hl2(Wrh[s], Wrh[s + 1]);
        g_Whh[i]           = f2hl2(Whh[s], Whh[s + 1]);
    }
    if (i < 1536) g_bias[i] = (i < 512) ? bz[i] : (i < 1024 ? br[i - 512] : bh[i - 1024]);
    if (i < NB_ * D_) g_h[i] = 0.0f;
}

// ---------------- fused fp16x2 (3-product) GEMM ----------------
// C[M,N] = A[M,512] * B[N,512]^T.  512 threads, 4x4 warp grid, warptile (BM/4) x 32.
// K-tile = 32 floats = 16 k-pairs; row stride 22 uint2 (conflict-free).
// MODE 0: A=X,   B=W1,  -> g_xproj (+bias)
// MODE 1: A=g_h, B=Wg,  -> z -> g_z ; u = r*h -> g_u
// MODE 2: A=g_u, B=Whh, -> h update -> g_h, out
template <int MODE, int BM>
__global__ __launch_bounds__(512, 1) void gemm_k(const float* __restrict__ A_arg,
                                                 float* __restrict__ out, int t) {
    extern __shared__ uint2 sm2[];
    const int SROW = 22;                       // uint2 per smem row (16 data + 6 pad)
    const int ASTRIDE = BM * SROW;
    const int BSTRIDE = 128 * SROW;
    const int MI = BM / 64;                    // m16 tiles per warp row
    uint2* As = sm2;                           // [2][BM*22]
    uint2* Bs = sm2 + 2 * ASTRIDE;             // [2][128*22]

    const float* __restrict__ A = (MODE == 0) ? A_arg : (MODE == 1 ? g_h : g_u);
    const uint2* __restrict__ Bhl = (MODE == 0) ? g_W1h : (MODE == 1 ? g_Wgh : g_Whh);

    const int tid  = threadIdx.x;
    const int lane = tid & 31, warp = tid >> 5;
    const int wm = warp >> 2, wn = warp & 3;   // 4 x 4
    const int g  = lane >> 2, tg = lane & 3;
    const int bm = blockIdx.y * BM, bn = blockIdx.x * 128;

    // staging assignment: s -> (row = s>>3, c4 = s&7); each unit = one float4 / uint4 (2 k-pairs)
    const int arow = tid >> 3, ac4 = tid & 7;

    float acc[MI][4][4];
#pragma unroll
    for (int i = 0; i < MI; i++)
#pragma unroll
        for (int j = 0; j < 4; j++)
#pragma unroll
            for (int e = 0; e < 4; e++) acc[i][j][e] = 0.0f;

    const int AIT = (BM * 8 + 511) / 512;      // A staging iters (2 for BM=128, 1 for BM=64)
    float4 ra[AIT];
    uint4  rb[2];

    // ---- prologue: stage k-tile 0 ----
#pragma unroll
    for (int it = 0; it < AIT; it++) {
        int row = arow + it * 64;
        ra[it] = *(const float4*)(A + (size_t)(bm + row) * D_ + ac4 * 4);
    }
#pragma unroll
    for (int it = 0; it < 2; it++) {
        int row = arow + it * 64;
        rb[it] = *(const uint4*)(Bhl + (size_t)(bn + row) * KP_ + ac4 * 2);
    }
#pragma unroll
    for (int it = 0; it < AIT; it++) {
        int row = arow + it * 64;
        uint2 p0 = f2hl2(ra[it].x, ra[it].y);
        uint2 p1 = f2hl2(ra[it].z, ra[it].w);
        *(uint4*)(&As[row * SROW + ac4 * 2]) = make_uint4(p0.x, p0.y, p1.x, p1.y);
    }
#pragma unroll
    for (int it = 0; it < 2; it++) {
        int row = arow + it * 64;
        *(uint4*)(&Bs[row * SROW + ac4 * 2]) = rb[it];
    }
    __syncthreads();

    int buf = 0;
#pragma unroll 1
    for (int kt = 0; kt < 16; kt++) {
        if (kt < 15) {
            const float* Ag2 = A + (size_t)bm * D_ + (kt + 1) * 32 + ac4 * 4;
            const uint2* Bg2 = Bhl + (size_t)bn * KP_ + (kt + 1) * 16 + ac4 * 2;
#pragma unroll
            for (int it = 0; it < AIT; it++)
                ra[it] = *(const float4*)(Ag2 + (size_t)(arow + it * 64) * D_);
#pragma unroll
            for (int it = 0; it < 2; it++)
                rb[it] = *(const uint4*)(Bg2 + (size_t)(arow + it * 64) * KP_);
        }
        const uint2* Ab = As + buf * ASTRIDE;
        const uint2* Bb = Bs + buf * BSTRIDE;
#pragma unroll
        for (int kk = 0; kk < 2; kk++) {
            const int k0 = kk * 8;
            uint2 aa[MI][4], bb[4][2];
#pragma unroll
            for (int i = 0; i < MI; i++) {
                const int r0 = wm * (BM / 4) + i * 16 + g;
                aa[i][0] = Ab[r0 * SROW + k0 + tg];
                aa[i][1] = Ab[(r0 + 8) * SROW + k0 + tg];
                aa[i][2] = Ab[r0 * SROW + k0 + tg + 4];
                aa[i][3] = Ab[(r0 + 8) * SROW + k0 + tg + 4];
            }
#pragma unroll
            for (int j = 0; j < 4; j++) {
                const int n0 = wn * 32 + j * 8 + g;
                bb[j][0] = Bb[n0 * SROW + k0 + tg];
                bb[j][1] = Bb[n0 * SROW + k0 + tg + 4];
            }
            // hi*hi
#pragma unroll
            for (int i = 0; i < MI; i++) {
                unsigned ah[4] = {aa[i][0].x, aa[i][1].x, aa[i][2].x, aa[i][3].x};
#pragma unroll
                for (int j = 0; j < 4; j++) {
                    unsigned bh2[2] = {bb[j][0].x, bb[j][1].x};
                    mma16(acc[i][j], ah, bh2);
                }
            }
            // lo*hi
#pragma unroll
            for (int i = 0; i < MI; i++) {
                unsigned al[4] = {aa[i][0].y, aa[i][1].y, aa[i][2].y, aa[i][3].y};
#pragma unroll
                for (int j = 0; j < 4; j++) {
                    unsigned bh2[2] = {bb[j][0].x, bb[j][1].x};
                    mma16(acc[i][j], al, bh2);
                }
            }
            // hi*lo
#pragma unroll
            for (int i = 0; i < MI; i++) {
                unsigned ah[4] = {aa[i][0].x, aa[i][1].x, aa[i][2].x, aa[i][3].x};
#pragma unroll
                for (int j = 0; j < 4; j++) {
                    unsigned bl[2] = {bb[j][0].y, bb[j][1].y};
                    mma16(acc[i][j], ah, bl);
                }
            }
        }
        if (kt < 15) {
            uint2* An = As + (buf ^ 1) * ASTRIDE;
            uint2* Bn = Bs + (buf ^ 1) * BSTRIDE;
#pragma unroll
            for (int it = 0; it < AIT; it++) {
                int row = arow + it * 64;
                uint2 p0 = f2hl2(ra[it].x, ra[it].y);
                uint2 p1 = f2hl2(ra[it].z, ra[it].w);
                *(uint4*)(&An[row * SROW + ac4 * 2]) = make_uint4(p0.x, p0.y, p1.x, p1.y);
            }
#pragma unroll
            for (int it = 0; it < 2; it++) {
                int row = arow + it * 64;
                *(uint4*)(&Bn[row * SROW + ac4 * 2]) = rb[it];
            }
            __syncthreads();
        }
        buf ^= 1;
    }

    // ---------------- epilogue ----------------
#pragma unroll
    for (int i = 0; i < MI; i++) {
#pragma unroll
        for (int j = 0; j < 4; j++) {
#pragma unroll
            for (int e = 0; e < 4; e++) {
                const int row = bm + wm * (BM / 4) + i * 16 + g + ((e >> 1) << 3);
                const int col = bn + wn * 32 + j * 8 + (tg << 1) + (e & 1);
                float v = acc[i][j][e];
                if (MODE == 0) {
                    v += g_bias[col];
                    g_xproj[(size_t)row * 1536 + col] = v;
                } else if (MODE == 1) {
                    const size_t xb = ((size_t)row * TT_ + t) * 1536;
                    if (col < 512) {
                        g_z[row * D_ + col] = sigmoidf_(v + g_xproj[xb + col]);
                    } else {
                        const int c = col - 512;
                        float rr = sigmoidf_(v + g_xproj[xb + 512 + c]);
                        g_u[row * D_ + c] = rr * g_h[row * D_ + c];
                    }
                } else {
                    const size_t xb = ((size_t)row * TT_ + t) * 1536;
                    float ht = tanhf(v + g_xproj[xb + 1024 + col]);
                    float zz = g_z[row * D_ + col];
                    float ho = g_h[row * D_ + col];
                    float hn = zz * ho + (1.0f - zz) * ht;
                    g_h[row * D_ + col] = hn;
                    out[((size_t)row * TT_ + t) * D_ + col] = hn;
                }
            }
        }
    }
}

// ---------------- launch ----------------
extern "C" void kernel_launch(void* const* d_in, const int* in_sizes, int n_in,
                              void* d_out, int out_size) {
    const float* X   = (const float*)d_in[0];
    const float* Wzx = (const float*)d_in[1];
    const float* Wzh = (const float*)d_in[2];
    const float* Wrx = (const float*)d_in[3];
    const float* Wrh = (const float*)d_in[4];
    const float* Whx = (const float*)d_in[5];
    const float* Whh = (const float*)d_in[6];
    const float* bz  = (const float*)d_in[7];
    const float* br  = (const float*)d_in[8];
    const float* bh  = (const float*)d_in[9];
    float* out = (float*)d_out;

    const int SROW = 22;
    const int SMEM128 = (2 * 128 * SROW + 2 * 128 * SROW) * (int)sizeof(uint2); // 90112
    const int SMEM64  = (2 * 64 * SROW + 2 * 128 * SROW) * (int)sizeof(uint2);  // 67584
    cudaFuncSetAttribute((const void*)gemm_k<0, 128>, cudaFuncAttributeMaxDynamicSharedMemorySize, SMEM128);
    cudaFuncSetAttribute((const void*)gemm_k<1, 128>, cudaFuncAttributeMaxDynamicSharedMemorySize, SMEM128);
    cudaFuncSetAttribute((const void*)gemm_k<2, 64>,  cudaFuncAttributeMaxDynamicSharedMemorySize, SMEM64);

    prep_kernel<<<(NB_ * D_ + 255) / 256, 256>>>(Wzx, Wzh, Wrx, Wrh, Whx, Whh, bz, br, bh);

    // Phase 1: time-parallel input projections [131072 x 1536]
    gemm_k<0, 128><<<dim3(1536 / 128, MT_ / 128), 512, SMEM128>>>(X, out, 0);

    // Phase 2: sequential recurrence (128 CTAs each, full chip)
    for (int t = 0; t < TT_; t++) {
        gemm_k<1, 128><<<dim3(1024 / 128, NB_ / 128), 512, SMEM128>>>(X, out, t);
        gemm_k<2, 64><<<dim3(512 / 128, NB_ / 64), 512, SMEM64>>>(X, out, t);
    }
}

// round 5
// speedup vs baseline: 2.4267x; 1.3634x over previous
#include <cuda_runtime.h>
#include <cuda_fp16.h>
#include <cstdint>
#include <math.h>

#define D_  512
#define NB_ 2048
#define TT_ 64
#define MT_ (NB_*TT_)

// tile images: [row_tile][k_tile] blocks of 32KB (16KB hi fp16 + 16KB lo fp16),
// each 128 rows x 64 cols fp16, SW128-swizzled, K-major.
#define TILE_BYTES 32768
#define NKT 8

__device__ __align__(128) unsigned char g_Ximg[(size_t)1024 * NKT * TILE_BYTES];
__device__ __align__(128) unsigned char g_W1img[12 * NKT * TILE_BYTES];
__device__ __align__(128) unsigned char g_Wgimg[8 * NKT * TILE_BYTES];
__device__ __align__(128) unsigned char g_Whimg[4 * NKT * TILE_BYTES];
__device__ __align__(128) unsigned char g_Himg[16 * NKT * TILE_BYTES];
__device__ __align__(128) unsigned char g_Uimg[16 * NKT * TILE_BYTES];
__device__ __align__(16) float g_xproj[(size_t)MT_ * 1536];
__device__ __align__(16) float g_bias[1536];
__device__ __align__(16) float g_h[NB_ * D_];
__device__ __align__(16) float g_z[NB_ * D_];

// ---------------- helpers ----------------
__device__ __forceinline__ uint32_t swz(uint32_t o) { return o ^ ((o >> 3) & 0x70); }

__device__ __forceinline__ void hl_pack(float x0, float x1, uint32_t& hi, uint32_t& lo) {
    __half h0 = __float2half_rn(x0), h1 = __float2half_rn(x1);
    __half l0 = __float2half_rn(x0 - __half2float(h0));
    __half l1 = __float2half_rn(x1 - __half2float(h1));
    hi = (uint32_t)__half_as_ushort(h0) | ((uint32_t)__half_as_ushort(h1) << 16);
    lo = (uint32_t)__half_as_ushort(l0) | ((uint32_t)__half_as_ushort(l1) << 16);
}

__device__ __forceinline__ void img_write_pair(unsigned char* img, int rt, int kt,
                                               int irow, int jj, float x0, float x1) {
    uint32_t hi, lo;
    hl_pack(x0, x1, hi, lo);
    size_t blk = ((size_t)rt * NKT + kt) * TILE_BYTES;
    uint32_t off = swz((uint32_t)irow * 128 + (uint32_t)jj * 4);
    *(uint32_t*)(img + blk + off) = hi;
    *(uint32_t*)(img + blk + 16384 + off) = lo;
}

__device__ __forceinline__ uint32_t smem_u32(const void* p) {
    uint32_t r;
    asm("{ .reg .u64 t; cvta.to.shared.u64 t, %1; cvt.u32.u64 %0, t; }" : "=r"(r) : "l"(p));
    return r;
}
__device__ __forceinline__ void cpa16(uint32_t dst, const void* src) {
    asm volatile("cp.async.cg.shared.global [%0], [%1], 16;" :: "r"(dst), "l"(src));
}
__device__ __forceinline__ void cpa_commit() { asm volatile("cp.async.commit_group;" ::: "memory"); }
__device__ __forceinline__ void cpa_wait1() { asm volatile("cp.async.wait_group 1;" ::: "memory"); }
__device__ __forceinline__ void cpa_wait0() { asm volatile("cp.async.wait_group 0;" ::: "memory"); }

__device__ __forceinline__ void ldsm4(uint32_t* r, uint32_t addr) {
    asm volatile("ldmatrix.sync.aligned.m8n8.x4.shared.b16 {%0,%1,%2,%3}, [%4];"
                 : "=r"(r[0]), "=r"(r[1]), "=r"(r[2]), "=r"(r[3]) : "r"(addr));
}
__device__ __forceinline__ void mma16(float* d, const uint32_t* a, const uint32_t* b) {
    asm volatile(
        "mma.sync.aligned.m16n8k16.row.col.f32.f16.f16.f32 "
        "{%0,%1,%2,%3},{%4,%5,%6,%7},{%8,%9},{%0,%1,%2,%3};"
        : "+f"(d[0]), "+f"(d[1]), "+f"(d[2]), "+f"(d[3])
        : "r"(a[0]), "r"(a[1]), "r"(a[2]), "r"(a[3]), "r"(b[0]), "r"(b[1]));
}
__device__ __forceinline__ float sigmoidf_(float x) { return 1.0f / (1.0f + expf(-x)); }

// ---------------- prep ----------------
__global__ void prep_weights(const float* __restrict__ Wzx, const float* __restrict__ Wzh,
                             const float* __restrict__ Wrx, const float* __restrict__ Wrh,
                             const float* __restrict__ Whx, const float* __restrict__ Whh,
                             const float* __restrict__ bz, const float* __restrict__ br,
                             const float* __restrict__ bh) {
    int i = blockIdx.x * 256 + threadIdx.x;      // 1536 blocks
    int n = i >> 8, jp = i & 255;
    int kt = jp >> 5, jj = jp & 31, k = jp * 2;
    {
        const float* s = (n < 512) ? Wzx : (n < 1024 ? Wrx : Whx);
        int nn = (n < 512) ? n : (n < 1024 ? n - 512 : n - 1024);
        img_write_pair(g_W1img, n >> 7, kt, n & 127, jj, s[nn * 512 + k], s[nn * 512 + k + 1]);
    }
    if (n < 1024) {
        const float* s = (n < 512) ? Wzh : Wrh;
        int nn = n & 511;
        img_write_pair(g_Wgimg, n >> 7, kt, n & 127, jj, s[nn * 512 + k], s[nn * 512 + k + 1]);
    }
    if (n < 512)
        img_write_pair(g_Whimg, n >> 7, kt, n & 127, jj, Whh[n * 512 + k], Whh[n * 512 + k + 1]);
    if (i < 1536) g_bias[i] = (i < 512) ? bz[i] : (i < 1024 ? br[i - 512] : bh[i - 1024]);
    if (i < NB_ * D_ / 4) ((float4*)g_h)[i] = make_float4(0.f, 0.f, 0.f, 0.f);
    if (i < 16 * NKT * TILE_BYTES / 16) ((uint4*)g_Himg)[i] = make_uint4(0, 0, 0, 0);
}

__global__ void prep_x(const float* __restrict__ X) {
    int i = blockIdx.x * 256 + threadIdx.x;      // 131072 blocks
    int row = i >> 8, jp = i & 255;
    float2 v = *(const float2*)(X + (size_t)row * 512 + jp * 2);
    img_write_pair(g_Ximg, row >> 7, jp >> 5, row & 127, jp & 31, v.x, v.y);
}

// ---------------- HMMA GEMM on pre-swizzled fp16 hi/lo images ----------------
// CTA 128 x BN, 256 thr, warp grid 4(m) x 2(n), warptile 32 x (BN/2).
// MODE 0: A=Ximg, B=W1img -> xproj(+bias)   grid (12,1024), BN=128
// MODE 1: A=Himg, B=Wgimg -> z, u-image     grid (8,16),   BN=128
// MODE 2: A=Uimg, B=Whimg -> h update       grid (8,16),   BN=64
template <int MODE, int BN>
__global__ __launch_bounds__(256, 1) void gemm_hm(float* __restrict__ out, int t) {
    extern __shared__ __align__(1024) unsigned char sm[];
    const uint32_t smb = smem_u32(sm);
    constexpr int BPL  = BN * 128;          // bytes per B plane
    constexpr int SBUF = 32768 + 2 * BPL;   // one buffer: A(hi+lo) + B(hi+lo)
    constexpr int NT = BN / 16;             // n8 tiles per warp
    constexpr int NP = BN / 32;             // ldmatrix.x4 groups per plane (B)

    const unsigned char* __restrict__ Aimg = (MODE == 0) ? g_Ximg : (MODE == 1 ? g_Himg : g_Uimg);
    const unsigned char* __restrict__ Bimg = (MODE == 0) ? g_W1img : (MODE == 1 ? g_Wgimg : g_Whimg);

    const int tid = threadIdx.x, lane = tid & 31, warp = tid >> 5;
    const int wm = warp >> 1, wn = warp & 1;
    const int bn = blockIdx.x, bm = blockIdx.y;

    // fragment address components (byte offsets within a plane)
    const int rx    = (lane & 7) << 4;
    const int colA  = (lane >> 4) << 4;
    const int colB  = ((lane >> 3) & 1) << 4;
    int rA[2], rB[NP];
#pragma unroll
    for (int mt = 0; mt < 2; mt++)
        rA[mt] = (wm * 32 + mt * 16 + (lane & 15)) * 128;
#pragma unroll
    for (int p = 0; p < NP; p++)
        rB[p] = (wn * (BN / 2) + p * 16 + (lane & 7) + ((lane >> 4) << 3)) * 128;

    float acc[2][NT][4];
#pragma unroll
    for (int i = 0; i < 2; i++)
#pragma unroll
        for (int j = 0; j < NT; j++)
#pragma unroll
            for (int e = 0; e < 4; e++) acc[i][j][e] = 0.0f;

    auto docopy = [&](int kt, int buf) {
        const uint32_t da = smb + buf * SBUF;
        const unsigned char* sa = Aimg + ((size_t)(bm * NKT + kt)) * TILE_BYTES;
#pragma unroll
        for (int i = 0; i < 8; i++)
            cpa16(da + (tid + i * 256) * 16, sa + (size_t)(tid + i * 256) * 16);
        if (BN == 128) {
            const uint32_t db = da + 32768;
            const unsigned char* sb = Bimg + ((size_t)(bn * NKT + kt)) * TILE_BYTES;
#pragma unroll
            for (int i = 0; i < 8; i++)
                cpa16(db + (tid + i * 256) * 16, sb + (size_t)(tid + i * 256) * 16);
        } else {
            const uint32_t db = da + 32768;
            const unsigned char* sb = Bimg + ((size_t)((bn >> 1) * NKT + kt)) * TILE_BYTES + (bn & 1) * 8192;
#pragma unroll
            for (int p = 0; p < 2; p++)
#pragma unroll
                for (int i = 0; i < 2; i++)
                    cpa16(db + p * 8192 + (tid + i * 256) * 16,
                          sb + (size_t)p * 16384 + (size_t)(tid + i * 256) * 16);
        }
    };

    docopy(0, 0);
    cpa_commit();

    int buf = 0;
#pragma unroll 1
    for (int kt = 0; kt < NKT; kt++) {
        if (kt < NKT - 1) {
            docopy(kt + 1, buf ^ 1);
            cpa_commit();
            cpa_wait1();
        } else {
            cpa_wait0();
        }
        __syncthreads();

        const uint32_t sA = smb + buf * SBUF;
        const uint32_t sB = sA + 32768;
#pragma unroll
        for (int k16 = 0; k16 < 4; k16++) {
            uint32_t Ah[2][4], Al[2][4];
#pragma unroll
            for (int mt = 0; mt < 2; mt++) {
                const uint32_t ad = sA + rA[mt] + ((k16 * 32 + colA) ^ rx);
                ldsm4(Ah[mt], ad);
                ldsm4(Al[mt], ad + 16384);
            }
            uint32_t Bh[NT][2], Bl[NT][2];
#pragma unroll
            for (int p = 0; p < NP; p++) {
                const uint32_t bd = sB + rB[p] + ((k16 * 32 + colB) ^ rx);
                uint32_t r4[4];
                ldsm4(r4, bd);
                Bh[2 * p][0] = r4[0]; Bh[2 * p][1] = r4[1];
                Bh[2 * p + 1][0] = r4[2]; Bh[2 * p + 1][1] = r4[3];
                ldsm4(r4, bd + BPL);
                Bl[2 * p][0] = r4[0]; Bl[2 * p][1] = r4[1];
                Bl[2 * p + 1][0] = r4[2]; Bl[2 * p + 1][1] = r4[3];
            }
#pragma unroll
            for (int mt = 0; mt < 2; mt++)
#pragma unroll
                for (int nt = 0; nt < NT; nt++) mma16(acc[mt][nt], Ah[mt], Bh[nt]);
#pragma unroll
            for (int mt = 0; mt < 2; mt++)
#pragma unroll
                for (int nt = 0; nt < NT; nt++) mma16(acc[mt][nt], Al[mt], Bh[nt]);
#pragma unroll
            for (int mt = 0; mt < 2; mt++)
#pragma unroll
                for (int nt = 0; nt < NT; nt++) mma16(acc[mt][nt], Ah[mt], Bl[nt]);
        }
        __syncthreads();
        buf ^= 1;
    }

    // ---------------- epilogue ----------------
    const int g = lane >> 2, tg = lane & 3;
    const int cbase = bn * BN + wn * (BN / 2);
#pragma unroll
    for (int mt = 0; mt < 2; mt++) {
#pragma unroll
        for (int nt = 0; nt < NT; nt++) {
            const int c = cbase + nt * 8 + tg * 2;
#pragma unroll
            for (int h2 = 0; h2 < 2; h2++) {
                const int irow = wm * 32 + mt * 16 + g + h2 * 8;
                const int row  = bm * 128 + irow;
                float v0 = acc[mt][nt][h2 * 2 + 0];
                float v1 = acc[mt][nt][h2 * 2 + 1];
                if (MODE == 0) {
                    float2 b = *(const float2*)(g_bias + c);
                    float2 o; o.x = v0 + b.x; o.y = v1 + b.y;
                    *(float2*)(g_xproj + (size_t)row * 1536 + c) = o;
                } else if (MODE == 1) {
                    const size_t xb = ((size_t)row * TT_ + t) * 1536;
                    float2 xp = *(const float2*)(g_xproj + xb + c);
                    if (c < 512) {
                        float2 zv; zv.x = sigmoidf_(v0 + xp.x); zv.y = sigmoidf_(v1 + xp.y);
                        *(float2*)(g_z + (size_t)row * 512 + c) = zv;
                    } else {
                        const int c2 = c - 512;
                        float2 hv = *(const float2*)(g_h + (size_t)row * 512 + c2);
                        float u0 = sigmoidf_(v0 + xp.x) * hv.x;
                        float u1 = sigmoidf_(v1 + xp.y) * hv.y;
                        uint32_t hi, lo;
                        hl_pack(u0, u1, hi, lo);
                        const size_t blk = ((size_t)bm * NKT + (c2 >> 6)) * TILE_BYTES;
                        const uint32_t off = swz((uint32_t)irow * 128 + (uint32_t)(c2 & 63) * 2);
                        *(uint32_t*)(g_Uimg + blk + off) = hi;
                        *(uint32_t*)(g_Uimg + blk + 16384 + off) = lo;
                    }
                } else {
                    const size_t xb = ((size_t)row * TT_ + t) * 1536;
                    float2 xp = *(const float2*)(g_xproj + xb + 1024 + c);
                    float2 zv = *(const float2*)(g_z + (size_t)row * 512 + c);
                    float2 hv = *(const float2*)(g_h + (size_t)row * 512 + c);
                    float hn0 = zv.x * hv.x + (1.0f - zv.x) * tanhf(v0 + xp.x);
                    float hn1 = zv.y * hv.y + (1.0f - zv.y) * tanhf(v1 + xp.y);
                    float2 hn; hn.x = hn0; hn.y = hn1;
                    *(float2*)(g_h + (size_t)row * 512 + c) = hn;
                    *(float2*)(out + ((size_t)row * TT_ + t) * 512 + c) = hn;
                    uint32_t hi, lo;
                    hl_pack(hn0, hn1, hi, lo);
                    const size_t blk = ((size_t)bm * NKT + (c >> 6)) * TILE_BYTES;
                    const uint32_t off = swz((uint32_t)irow * 128 + (uint32_t)(c & 63) * 2);
                    *(uint32_t*)(g_Himg + blk + off) = hi;
                    *(uint32_t*)(g_Himg + blk + 16384 + off) = lo;
                }
            }
        }
    }
}

// ---------------- launch ----------------
extern "C" void kernel_launch(void* const* d_in, const int* in_sizes, int n_in,
                              void* d_out, int out_size) {
    const float* X   = (const float*)d_in[0];
    const float* Wzx = (const float*)d_in[1];
    const float* Wzh = (const float*)d_in[2];
    const float* Wrx = (const float*)d_in[3];
    const float* Wrh = (const float*)d_in[4];
    const float* Whx = (const float*)d_in[5];
    const float* Whh = (const float*)d_in[6];
    const float* bz  = (const float*)d_in[7];
    const float* br  = (const float*)d_in[8];
    const float* bh  = (const float*)d_in[9];
    float* out = (float*)d_out;

    const int SMEM128 = 2 * (32768 + 2 * 128 * 128); // 131072
    const int SMEM64  = 2 * (32768 + 2 * 64 * 128);  // 98304
    cudaFuncSetAttribute((const void*)gemm_hm<0, 128>, cudaFuncAttributeMaxDynamicSharedMemorySize, SMEM128);
    cudaFuncSetAttribute((const void*)gemm_hm<1, 128>, cudaFuncAttributeMaxDynamicSharedMemorySize, SMEM128);
    cudaFuncSetAttribute((const void*)gemm_hm<2, 64>,  cudaFuncAttributeMaxDynamicSharedMemorySize, SMEM64);

    prep_weights<<<1536, 256>>>(Wzx, Wzh, Wrx, Wrh, Whx, Whh, bz, br, bh);
    prep_x<<<131072, 256>>>(X);

    // Phase 1: input projections [131072 x 1536]
    gemm_hm<0, 128><<<dim3(12, 1024), 256, SMEM128>>>(out, 0);

    // Phase 2: recurrence
    for (int t = 0; t < TT_; t++) {
        gemm_hm<1, 128><<<dim3(8, 16), 256, SMEM128>>>(out, t);
        gemm_hm<2, 64><<<dim3(8, 16), 256, SMEM64>>>(out, t);
    }
}

// round 6
// speedup vs baseline: 2.6442x; 1.0896x over previous
#include <cuda_runtime.h>
#include <cuda_fp16.h>
#include <cstdint>
#include <math.h>

#define D_  512
#define NB_ 2048
#define TT_ 64
#define MT_ (NB_*TT_)

#define TILE_BYTES 32768
#define NKT 8

__device__ __align__(128) unsigned char g_Ximg[(size_t)1024 * NKT * TILE_BYTES];
__device__ __align__(128) unsigned char g_W1img[12 * NKT * TILE_BYTES];
__device__ __align__(128) unsigned char g_Wgimg[8 * NKT * TILE_BYTES];
__device__ __align__(128) unsigned char g_Whimg[4 * NKT * TILE_BYTES];
__device__ __align__(128) unsigned char g_Himg[16 * NKT * TILE_BYTES];
__device__ __align__(128) unsigned char g_Uimg[16 * NKT * TILE_BYTES];
__device__ __align__(16) float g_xproj[(size_t)MT_ * 1536];
__device__ __align__(16) float g_bias[1536];
__device__ __align__(16) float g_h[NB_ * D_];
__device__ __align__(16) float g_z[NB_ * D_];
__device__ unsigned g_barc = 0;
__device__ unsigned g_barf = 0;

// ---------------- helpers ----------------
__device__ __forceinline__ uint32_t swz(uint32_t o) { return o ^ ((o >> 3) & 0x70); }

__device__ __forceinline__ void hl_pack(float x0, float x1, uint32_t& hi, uint32_t& lo) {
    __half h0 = __float2half_rn(x0), h1 = __float2half_rn(x1);
    __half l0 = __float2half_rn(x0 - __half2float(h0));
    __half l1 = __float2half_rn(x1 - __half2float(h1));
    hi = (uint32_t)__half_as_ushort(h0) | ((uint32_t)__half_as_ushort(h1) << 16);
    lo = (uint32_t)__half_as_ushort(l0) | ((uint32_t)__half_as_ushort(l1) << 16);
}

__device__ __forceinline__ void img_write_pair(unsigned char* img, int rt, int kt,
                                               int irow, int jj, float x0, float x1) {
    uint32_t hi, lo;
    hl_pack(x0, x1, hi, lo);
    size_t blk = ((size_t)rt * NKT + kt) * TILE_BYTES;
    uint32_t off = swz((uint32_t)irow * 128 + (uint32_t)jj * 4);
    *(uint32_t*)(img + blk + off) = hi;
    *(uint32_t*)(img + blk + 16384 + off) = lo;
}

__device__ __forceinline__ uint32_t smem_u32(const void* p) {
    uint32_t r;
    asm("{ .reg .u64 t; cvta.to.shared.u64 t, %1; cvt.u32.u64 %0, t; }" : "=r"(r) : "l"(p));
    return r;
}
__device__ __forceinline__ void cpa16(uint32_t dst, const void* src) {
    asm volatile("cp.async.cg.shared.global [%0], [%1], 16;" :: "r"(dst), "l"(src));
}
__device__ __forceinline__ void cpa_commit() { asm volatile("cp.async.commit_group;" ::: "memory"); }
__device__ __forceinline__ void cpa_wait1() { asm volatile("cp.async.wait_group 1;" ::: "memory"); }
__device__ __forceinline__ void cpa_wait0() { asm volatile("cp.async.wait_group 0;" ::: "memory"); }

__device__ __forceinline__ void ldsm4(uint32_t* r, uint32_t addr) {
    asm volatile("ldmatrix.sync.aligned.m8n8.x4.shared.b16 {%0,%1,%2,%3}, [%4];"
                 : "=r"(r[0]), "=r"(r[1]), "=r"(r[2]), "=r"(r[3]) : "r"(addr));
}
__device__ __forceinline__ void mma16(float* d, const uint32_t* a, const uint32_t* b) {
    asm volatile(
        "mma.sync.aligned.m16n8k16.row.col.f32.f16.f16.f32 "
        "{%0,%1,%2,%3},{%4,%5,%6,%7},{%8,%9},{%0,%1,%2,%3};"
        : "+f"(d[0]), "+f"(d[1]), "+f"(d[2]), "+f"(d[3])
        : "r"(a[0]), "r"(a[1]), "r"(a[2]), "r"(a[3]), "r"(b[0]), "r"(b[1]));
}
__device__ __forceinline__ float sigmoidf_(float x) { return 1.0f / (1.0f + expf(-x)); }

// ---------------- prep ----------------
__global__ void prep_weights(const float* __restrict__ Wzx, const float* __restrict__ Wzh,
                             const float* __restrict__ Wrx, const float* __restrict__ Wrh,
                             const float* __restrict__ Whx, const float* __restrict__ Whh,
                             const float* __restrict__ bz, const float* __restrict__ br,
                             const float* __restrict__ bh) {
    int i = blockIdx.x * 256 + threadIdx.x;
    int n = i >> 8, jp = i & 255;
    int kt = jp >> 5, jj = jp & 31, k = jp * 2;
    {
        const float* s = (n < 512) ? Wzx : (n < 1024 ? Wrx : Whx);
        int nn = (n < 512) ? n : (n < 1024 ? n - 512 : n - 1024);
        img_write_pair(g_W1img, n >> 7, kt, n & 127, jj, s[nn * 512 + k], s[nn * 512 + k + 1]);
    }
    if (n < 1024) {
        const float* s = (n < 512) ? Wzh : Wrh;
        int nn = n & 511;
        img_write_pair(g_Wgimg, n >> 7, kt, n & 127, jj, s[nn * 512 + k], s[nn * 512 + k + 1]);
    }
    if (n < 512)
        img_write_pair(g_Whimg, n >> 7, kt, n & 127, jj, Whh[n * 512 + k], Whh[n * 512 + k + 1]);
    if (i < 1536) g_bias[i] = (i < 512) ? bz[i] : (i < 1024 ? br[i - 512] : bh[i - 1024]);
    if (i < NB_ * D_ / 4) ((float4*)g_h)[i] = make_float4(0.f, 0.f, 0.f, 0.f);
    if (i < 16 * NKT * TILE_BYTES / 16) ((uint4*)g_Himg)[i] = make_uint4(0, 0, 0, 0);
}

__global__ void prep_x(const float* __restrict__ X) {
    int i = blockIdx.x * 256 + threadIdx.x;
    int row = i >> 8, jp = i & 255;
    float2 v = *(const float2*)(X + (size_t)row * 512 + jp * 2);
    img_write_pair(g_Ximg, row >> 7, jp >> 5, row & 127, jp & 31, v.x, v.y);
}

// ---------------- GEMM core: 128 x BN tile, K=512, 512 thr, 3-stage cp.async ----
// acc layout: acc[mt*NT + nt][4], mt<2, NT = BN/32. Warp grid 4(m) x 4(n).
template <int BN>
__device__ __forceinline__ void gemm_core(uint32_t smb,
                                          const unsigned char* __restrict__ Asrc0,
                                          const unsigned char* __restrict__ Bsrc0,
                                          float (*acc)[4]) {
    constexpr int NT = BN / 32;
    constexpr int BPL = BN * 128;
    constexpr int SBUF = 32768 + 2 * BPL;
    const int tid = threadIdx.x, lane = tid & 31, warp = tid >> 5;
    const int wm = warp >> 2, wn = warp & 3;
    const int rx = (lane & 7) << 4;
    const int colA = (lane >> 4) << 4;
    const int colB = ((lane >> 3) & 1) << 4;
    int rA[2], rB[NT / 2];
#pragma unroll
    for (int mt = 0; mt < 2; mt++)
        rA[mt] = (wm * 32 + mt * 16 + (lane & 15)) * 128;
#pragma unroll
    for (int p = 0; p < NT / 2; p++)
        rB[p] = (wn * (BN / 4) + p * 16 + (lane & 7) + ((lane >> 4) << 3)) * 128;

    auto docopy = [&](int kt) {
        const int st = kt % 3;
        const uint32_t da = smb + st * SBUF;
        const unsigned char* sa = Asrc0 + (size_t)kt * TILE_BYTES;
#pragma unroll
        for (int i = 0; i < 4; i++)
            cpa16(da + (tid + i * 512) * 16, sa + (size_t)(tid + i * 512) * 16);
        const uint32_t db = da + 32768;
        const unsigned char* sb = Bsrc0 + (size_t)kt * TILE_BYTES;
#pragma unroll
        for (int p = 0; p < 2; p++)
#pragma unroll
            for (int i = 0; i < BN / 64; i++)
                cpa16(db + p * BPL + (tid + i * 512) * 16,
                      sb + (size_t)p * 16384 + (size_t)(tid + i * 512) * 16);
    };

    docopy(0); cpa_commit();
    docopy(1); cpa_commit();

#pragma unroll 1
    for (int kt = 0; kt < NKT; kt++) {
        if (kt < NKT - 1) cpa_wait1(); else cpa_wait0();
        __syncthreads();
        if (kt + 2 < NKT) { docopy(kt + 2); cpa_commit(); }

        const uint32_t sA = smb + (kt % 3) * SBUF;
        const uint32_t sB = sA + 32768;
#pragma unroll
        for (int k16 = 0; k16 < 4; k16++) {
            uint32_t Ah[2][4], Al[2][4];
#pragma unroll
            for (int mt = 0; mt < 2; mt++) {
                const uint32_t ad = sA + rA[mt] + ((k16 * 32 + colA) ^ rx);
                ldsm4(Ah[mt], ad);
                ldsm4(Al[mt], ad + 16384);
            }
            uint32_t Bh[NT][2], Bl[NT][2];
#pragma unroll
            for (int p = 0; p < NT / 2; p++) {
                const uint32_t bd = sB + rB[p] + ((k16 * 32 + colB) ^ rx);
                uint32_t r4[4];
                ldsm4(r4, bd);
                Bh[2 * p][0] = r4[0]; Bh[2 * p][1] = r4[1];
                Bh[2 * p + 1][0] = r4[2]; Bh[2 * p + 1][1] = r4[3];
                ldsm4(r4, bd + BPL);
                Bl[2 * p][0] = r4[0]; Bl[2 * p][1] = r4[1];
                Bl[2 * p + 1][0] = r4[2]; Bl[2 * p + 1][1] = r4[3];
            }
#pragma unroll
            for (int mt = 0; mt < 2; mt++)
#pragma unroll
                for (int nt = 0; nt < NT; nt++) mma16(acc[mt * NT + nt], Ah[mt], Bh[nt]);
#pragma unroll
            for (int mt = 0; mt < 2; mt++)
#pragma unroll
                for (int nt = 0; nt < NT; nt++) mma16(acc[mt * NT + nt], Al[mt], Bh[nt]);
#pragma unroll
            for (int mt = 0; mt < 2; mt++)
#pragma unroll
                for (int nt = 0; nt < NT; nt++) mma16(acc[mt * NT + nt], Ah[mt], Bl[nt]);
        }
    }
    __syncthreads();
}

// ---------------- phase-1 kernel: xproj = X @ W1^T + bias ----------------
__global__ __launch_bounds__(512, 1) void gemm0_k(float* __restrict__ out) {
    extern __shared__ __align__(1024) unsigned char sm[];
    const uint32_t smb = smem_u32(sm);
    const int tid = threadIdx.x, lane = tid & 31, warp = tid >> 5;
    const int wm = warp >> 2, wn = warp & 3, g = lane >> 2, tg = lane & 3;
    const int bn = blockIdx.x, bm = blockIdx.y;

    float acc[8][4];
#pragma unroll
    for (int i = 0; i < 8; i++)
#pragma unroll
        for (int e = 0; e < 4; e++) acc[i][e] = 0.0f;

    gemm_core<128>(smb, g_Ximg + (size_t)bm * NKT * TILE_BYTES,
                   g_W1img + (size_t)bn * NKT * TILE_BYTES, acc);

    const int cbase = bn * 128 + wn * 32;
#pragma unroll
    for (int mt = 0; mt < 2; mt++)
#pragma unroll
        for (int nt = 0; nt < 4; nt++) {
            const int c = cbase + nt * 8 + tg * 2;
            float2 b = *(const float2*)(g_bias + c);
#pragma unroll
            for (int h2 = 0; h2 < 2; h2++) {
                const int row = bm * 128 + wm * 32 + mt * 16 + g + h2 * 8;
                float2 o;
                o.x = acc[mt * 4 + nt][h2 * 2 + 0] + b.x;
                o.y = acc[mt * 4 + nt][h2 * 2 + 1] + b.y;
                *(float2*)(g_xproj + (size_t)row * 1536 + c) = o;
            }
        }
}

// ---------------- fused per-step kernel: phase A (gates) + barrier + phase B (h) ----
__global__ __launch_bounds__(512, 1) void step_k(float* __restrict__ out, int t) {
    extern __shared__ __align__(1024) unsigned char sm[];
    const uint32_t smb = smem_u32(sm);
    const int tid = threadIdx.x, lane = tid & 31, warp = tid >> 5;
    const int wm = warp >> 2, wn = warp & 3, g = lane >> 2, tg = lane & 3;
    const int bm = blockIdx.x >> 3, bn = blockIdx.x & 7;

    // ================= phase A: [z|r] = h @ Wg^T =================
    {
        float acc[8][4];
#pragma unroll
        for (int i = 0; i < 8; i++)
#pragma unroll
            for (int e = 0; e < 4; e++) acc[i][e] = 0.0f;

        gemm_core<128>(smb, g_Himg + (size_t)bm * NKT * TILE_BYTES,
                       g_Wgimg + (size_t)bn * NKT * TILE_BYTES, acc);

        const int cbase = bn * 128 + wn * 32;
#pragma unroll
        for (int mt = 0; mt < 2; mt++)
#pragma unroll
            for (int nt = 0; nt < 4; nt++) {
                const int c = cbase + nt * 8 + tg * 2;
#pragma unroll
                for (int h2 = 0; h2 < 2; h2++) {
                    const int irow = wm * 32 + mt * 16 + g + h2 * 8;
                    const int row = bm * 128 + irow;
                    float v0 = acc[mt * 4 + nt][h2 * 2 + 0];
                    float v1 = acc[mt * 4 + nt][h2 * 2 + 1];
                    const size_t xb = ((size_t)row * TT_ + t) * 1536;
                    float2 xp = *(const float2*)(g_xproj + xb + c);
                    if (cbase < 512) {
                        float2 zv;
                        zv.x = sigmoidf_(v0 + xp.x);
                        zv.y = sigmoidf_(v1 + xp.y);
                        *(float2*)(g_z + (size_t)row * 512 + c) = zv;
                    } else {
                        const int c2 = c - 512;
                        float2 hv = *(const float2*)(g_h + (size_t)row * 512 + c2);
                        float u0 = sigmoidf_(v0 + xp.x) * hv.x;
                        float u1 = sigmoidf_(v1 + xp.y) * hv.y;
                        uint32_t hi, lo;
                        hl_pack(u0, u1, hi, lo);
                        const size_t blk = ((size_t)bm * NKT + (c2 >> 6)) * TILE_BYTES;
                        const uint32_t off = swz((uint32_t)irow * 128 + (uint32_t)(c2 & 63) * 2);
                        *(uint32_t*)(g_Uimg + blk + off) = hi;
                        *(uint32_t*)(g_Uimg + blk + 16384 + off) = lo;
                    }
                }
            }
    }

    // ================= grid-wide barrier =================
    __threadfence();
    __syncthreads();
    if (tid == 0) {
        unsigned entry = *(volatile unsigned*)&g_barf;
        unsigned tk = atomicAdd(&g_barc, 1);
        if (tk == gridDim.x - 1) {
            g_barc = 0;
            __threadfence();
            atomicAdd(&g_barf, 1);
        } else {
            while (*(volatile unsigned*)&g_barf == entry) { }
        }
        __threadfence();
    }
    __syncthreads();

    // ================= phase B: h_tilde = u @ Whh^T ; h update =================
    {
        float acc[4][4];
#pragma unroll
        for (int i = 0; i < 4; i++)
#pragma unroll
            for (int e = 0; e < 4; e++) acc[i][e] = 0.0f;

        gemm_core<64>(smb, g_Uimg + (size_t)bm * NKT * TILE_BYTES,
                      g_Whimg + (size_t)((bn >> 1) * NKT) * TILE_BYTES + (bn & 1) * 8192, acc);

#pragma unroll
        for (int mt = 0; mt < 2; mt++)
#pragma unroll
            for (int nt = 0; nt < 2; nt++) {
                const int c = bn * 64 + wn * 16 + nt * 8 + tg * 2;
#pragma unroll
                for (int h2 = 0; h2 < 2; h2++) {
                    const int irow = wm * 32 + mt * 16 + g + h2 * 8;
                    const int row = bm * 128 + irow;
                    float v0 = acc[mt * 2 + nt][h2 * 2 + 0];
                    float v1 = acc[mt * 2 + nt][h2 * 2 + 1];
                    const size_t xb = ((size_t)row * TT_ + t) * 1536;
                    float2 xp = *(const float2*)(g_xproj + xb + 1024 + c);
                    float2 zv = *(const float2*)(g_z + (size_t)row * 512 + c);
                    float2 hv = *(const float2*)(g_h + (size_t)row * 512 + c);
                    float hn0 = zv.x * hv.x + (1.0f - zv.x) * tanhf(v0 + xp.x);
                    float hn1 = zv.y * hv.y + (1.0f - zv.y) * tanhf(v1 + xp.y);
                    float2 hn; hn.x = hn0; hn.y = hn1;
                    *(float2*)(g_h + (size_t)row * 512 + c) = hn;
                    *(float2*)(out + ((size_t)row * TT_ + t) * 512 + c) = hn;
                    uint32_t hi, lo;
                    hl_pack(hn0, hn1, hi, lo);
                    const size_t blk = ((size_t)bm * NKT + (c >> 6)) * TILE_BYTES;
                    const uint32_t off = swz((uint32_t)irow * 128 + (uint32_t)(c & 63) * 2);
                    *(uint32_t*)(g_Himg + blk + off) = hi;
                    *(uint32_t*)(g_Himg + blk + 16384 + off) = lo;
                }
            }
    }
}

// ---------------- launch ----------------
extern "C" void kernel_launch(void* const* d_in, const int* in_sizes, int n_in,
                              void* d_out, int out_size) {
    const float* X   = (const float*)d_in[0];
    const float* Wzx = (const float*)d_in[1];
    const float* Wzh = (const float*)d_in[2];
    const float* Wrx = (const float*)d_in[3];
    const float* Wrh = (const float*)d_in[4];
    const float* Whx = (const float*)d_in[5];
    const float* Whh = (const float*)d_in[6];
    const float* bz  = (const float*)d_in[7];
    const float* br  = (const float*)d_in[8];
    const float* bh  = (const float*)d_in[9];
    float* out = (float*)d_out;

    const int SMEM = 3 * (32768 + 32768);   // 196608
    cudaFuncSetAttribute((const void*)gemm0_k, cudaFuncAttributeMaxDynamicSharedMemorySize, SMEM);
    cudaFuncSetAttribute((const void*)step_k, cudaFuncAttributeMaxDynamicSharedMemorySize, SMEM);

    prep_weights<<<1536, 256>>>(Wzx, Wzh, Wrx, Wrh, Whx, Whh, bz, br, bh);
    prep_x<<<131072, 256>>>(X);

    gemm0_k<<<dim3(12, 1024), 512, SMEM>>>(out);

    for (int t = 0; t < TT_; t++)
        step_k<<<128, 512, SMEM>>>(out, t);
}